// round 1
// baseline (speedup 1.0000x reference)
#include <cuda_runtime.h>

#define B_    2
#define N_    2048
#define DIM_  1024
#define H_    16
#define D_    64
#define E3_   3072
#define SCALE_ 0.125f

// Scratch (no allocations allowed): 4 x 16MB
__device__ float g_Q[B_ * H_ * N_ * D_];
__device__ float g_K[B_ * H_ * N_ * D_];
__device__ float g_V[B_ * H_ * N_ * D_];
__device__ float g_AO[B_ * N_ * DIM_];

// ---------------------------------------------------------------------------
// Generic fp32 GEMM: C[M,Nn] = A[M,K] @ W[Nn,K]^T + bias[Nn]
// MODE 0: plain write to C
// MODE 1: QKV epilogue — scatter into g_Q (scaled), g_K, g_V in [B,H,N,D]
// Block tile 128x128, K-chunk 16, 256 threads, 8x8 per thread.
// ---------------------------------------------------------------------------
template <int MODE>
__global__ __launch_bounds__(256) void sgemm_kernel(
    const float* __restrict__ A, const float* __restrict__ W,
    const float* __restrict__ bias, float* __restrict__ C,
    int M, int Nn, int K)
{
    __shared__ float As[16][132];
    __shared__ float Bs[16][132];

    const int tid = threadIdx.x;
    const int bm  = blockIdx.y * 128;
    const int bn  = blockIdx.x * 128;
    const int tx  = tid & 15;
    const int ty  = tid >> 4;
    const int lrow = tid >> 2;          // 0..63
    const int lcol = (tid & 3) << 2;    // 0,4,8,12

    float acc[8][8];
#pragma unroll
    for (int i = 0; i < 8; i++)
#pragma unroll
        for (int j = 0; j < 8; j++) acc[i][j] = 0.f;

    for (int k0 = 0; k0 < K; k0 += 16) {
#pragma unroll
        for (int rr = 0; rr < 2; rr++) {
            int r = lrow + rr * 64;
            float4 va = *(const float4*)(A + (size_t)(bm + r) * K + k0 + lcol);
            As[lcol + 0][r] = va.x; As[lcol + 1][r] = va.y;
            As[lcol + 2][r] = va.z; As[lcol + 3][r] = va.w;
            float4 vb = *(const float4*)(W + (size_t)(bn + r) * K + k0 + lcol);
            Bs[lcol + 0][r] = vb.x; Bs[lcol + 1][r] = vb.y;
            Bs[lcol + 2][r] = vb.z; Bs[lcol + 3][r] = vb.w;
        }
        __syncthreads();
#pragma unroll
        for (int kk = 0; kk < 16; kk++) {
            float a[8], b[8];
#pragma unroll
            for (int i = 0; i < 8; i++) a[i] = As[kk][ty * 8 + i];
#pragma unroll
            for (int j = 0; j < 8; j++) b[j] = Bs[kk][tx * 8 + j];
#pragma unroll
            for (int i = 0; i < 8; i++)
#pragma unroll
                for (int j = 0; j < 8; j++) acc[i][j] += a[i] * b[j];
        }
        __syncthreads();
    }

    if (MODE == 0) {
#pragma unroll
        for (int i = 0; i < 8; i++) {
            int m = bm + ty * 8 + i;
#pragma unroll
            for (int j = 0; j < 8; j++) {
                int n = bn + tx * 8 + j;
                C[(size_t)m * Nn + n] = acc[i][j] + bias[n];
            }
        }
    } else {
#pragma unroll
        for (int i = 0; i < 8; i++) {
            int m = bm + ty * 8 + i;
            int b = m >> 11;          // /2048
            int n = m & 2047;
#pragma unroll
            for (int j = 0; j < 8; j++) {
                int e = bn + tx * 8 + j;
                float v = acc[i][j] + bias[e];
                int which = e >> 10;          // 0=q,1=k,2=v
                int h = (e >> 6) & 15;
                int d = e & 63;
                size_t idx = ((size_t)(b * H_ + h) * N_ + n) * D_ + d;
                if (which == 0)      g_Q[idx] = v * SCALE_;
                else if (which == 1) g_K[idx] = v;
                else                 g_V[idx] = v;
            }
        }
    }
}

// ---------------------------------------------------------------------------
// Attention: per block = (b, h, 64 query rows). Online softmax over k-tiles
// of 32. O accumulator in registers (4x4 per thread). Bias streamed from gmem.
// ---------------------------------------------------------------------------
__global__ __launch_bounds__(256) void attn_kernel(
    const float* __restrict__ bias, const unsigned char* __restrict__ mask)
{
    __shared__ float Qs[64][65];
    __shared__ float Ks[32][65];
    __shared__ float Vs[32][68];
    __shared__ float Ss[64][33];
    __shared__ float mrow[64], lrow[64], arow[64];

    const int tid = threadIdx.x;
    const int b = blockIdx.z, h = blockIdx.y;
    const int q0 = blockIdx.x * 64;
    const int tx = tid & 15, ty = tid >> 4;

    const float* Qg = g_Q + (size_t)(b * H_ + h) * N_ * D_;
    const float* Kg = g_K + (size_t)(b * H_ + h) * N_ * D_;
    const float* Vg = g_V + (size_t)(b * H_ + h) * N_ * D_;
    const float* biash = bias + (size_t)h * N_ * N_;
    const unsigned char* maskb = mask + (size_t)b * N_;

    // Load Q tile (64x64)
#pragma unroll
    for (int t = 0; t < 4; t++) {
        int idx = tid + t * 256;            // 0..1023
        int r = idx >> 4;
        int c4 = (idx & 15) << 2;
        float4 v = *(const float4*)(Qg + (size_t)(q0 + r) * D_ + c4);
        Qs[r][c4] = v.x; Qs[r][c4 + 1] = v.y; Qs[r][c4 + 2] = v.z; Qs[r][c4 + 3] = v.w;
    }
    if (tid < 64) { mrow[tid] = -1e30f; lrow[tid] = 0.f; }

    float o[4][4];
#pragma unroll
    for (int i = 0; i < 4; i++)
#pragma unroll
        for (int j = 0; j < 4; j++) o[i][j] = 0.f;

    __syncthreads();

    for (int kt = 0; kt < N_; kt += 32) {
        // Load K,V tiles (32x64 each)
#pragma unroll
        for (int t = 0; t < 2; t++) {
            int idx = tid + t * 256;        // 0..511
            int r = idx >> 4;
            int c4 = (idx & 15) << 2;
            float4 vk = *(const float4*)(Kg + (size_t)(kt + r) * D_ + c4);
            Ks[r][c4] = vk.x; Ks[r][c4 + 1] = vk.y; Ks[r][c4 + 2] = vk.z; Ks[r][c4 + 3] = vk.w;
            float4 vv = *(const float4*)(Vg + (size_t)(kt + r) * D_ + c4);
            Vs[r][c4] = vv.x; Vs[r][c4 + 1] = vv.y; Vs[r][c4 + 2] = vv.z; Vs[r][c4 + 3] = vv.w;
        }
        __syncthreads();

        // Phase A: S[64][32] = Q @ K^T  (Q already pre-scaled)
        float s[4][2];
#pragma unroll
        for (int i = 0; i < 4; i++) { s[i][0] = 0.f; s[i][1] = 0.f; }
#pragma unroll
        for (int d = 0; d < 64; d++) {
            float qv[4], kv[2];
#pragma unroll
            for (int i = 0; i < 4; i++) qv[i] = Qs[ty * 4 + i][d];
#pragma unroll
            for (int j = 0; j < 2; j++) kv[j] = Ks[tx * 2 + j][d];
#pragma unroll
            for (int i = 0; i < 4; i++)
#pragma unroll
                for (int j = 0; j < 2; j++) s[i][j] += qv[i] * kv[j];
        }
        // Bias + mask, write S to smem
#pragma unroll
        for (int i = 0; i < 4; i++) {
            int q = q0 + ty * 4 + i;
            const float* brow = biash + (size_t)q * N_ + kt;
#pragma unroll
            for (int j = 0; j < 2; j++) {
                int kc = tx * 2 + j;
                float v = s[i][j] + brow[kc];
                if (maskb[kt + kc]) v = -1e30f;
                Ss[ty * 4 + i][kc] = v;
            }
        }
        __syncthreads();

        // Row stats: tile max, alpha, running max
        if (tid < 64) {
            float tmax = -1e30f;
#pragma unroll
            for (int j = 0; j < 32; j++) tmax = fmaxf(tmax, Ss[tid][j]);
            float mo = mrow[tid];
            float mn = fmaxf(mo, tmax);
            arow[tid] = __expf(mo - mn);
            mrow[tid] = mn;
        }
        __syncthreads();

        // exp (distributed across all 256 threads)
#pragma unroll
        for (int i = 0; i < 4; i++) {
            int r = ty * 4 + i;
            float mn = mrow[r];
#pragma unroll
            for (int j = 0; j < 2; j++) {
                int kc = tx * 2 + j;
                Ss[r][kc] = __expf(Ss[r][kc] - mn);
            }
        }
        __syncthreads();

        // Row sums + l update
        if (tid < 64) {
            float ssum = 0.f;
#pragma unroll
            for (int j = 0; j < 32; j++) ssum += Ss[tid][j];
            lrow[tid] = lrow[tid] * arow[tid] + ssum;
        }

        // Scale O by alpha (arow stable since last sync)
#pragma unroll
        for (int i = 0; i < 4; i++) {
            float al = arow[ty * 4 + i];
#pragma unroll
            for (int j = 0; j < 4; j++) o[i][j] *= al;
        }

        // Phase B: O += P @ V
#pragma unroll
        for (int kk = 0; kk < 32; kk++) {
            float p[4], vv[4];
#pragma unroll
            for (int i = 0; i < 4; i++) p[i] = Ss[ty * 4 + i][kk];
#pragma unroll
            for (int j = 0; j < 4; j++) vv[j] = Vs[kk][tx * 4 + j];
#pragma unroll
            for (int i = 0; i < 4; i++)
#pragma unroll
                for (int j = 0; j < 4; j++) o[i][j] += p[i] * vv[j];
        }
        __syncthreads();
    }

    // Epilogue: O /= l, write [b, n, h*64+d]
#pragma unroll
    for (int i = 0; i < 4; i++) {
        int q = q0 + ty * 4 + i;
        float inv = 1.f / lrow[ty * 4 + i];
#pragma unroll
        for (int j = 0; j < 4; j++) {
            g_AO[(size_t)(b * N_ + q) * DIM_ + h * D_ + tx * 4 + j] = o[i][j] * inv;
        }
    }
}

// ---------------------------------------------------------------------------
extern "C" void kernel_launch(void* const* d_in, const int* in_sizes, int n_in,
                              void* d_out, int out_size)
{
    (void)in_sizes; (void)n_in; (void)out_size;
    const float* x         = (const float*)d_in[0];
    const float* attn_bias = (const float*)d_in[1];
    const unsigned char* key_padding_mask = (const unsigned char*)d_in[2];
    const float* qkv_w     = (const float*)d_in[3];
    const float* qkv_b     = (const float*)d_in[4];
    const float* proj_w    = (const float*)d_in[5];
    const float* proj_b    = (const float*)d_in[6];
    float* out = (float*)d_out;

    // 1) QKV projection + scatter to [B,H,N,D] (Q pre-scaled)
    dim3 g1(E3_ / 128, (B_ * N_) / 128);   // 24 x 32
    sgemm_kernel<1><<<g1, 256>>>(x, qkv_w, qkv_b, nullptr, B_ * N_, E3_, DIM_);

    // 2) Attention with online softmax (+bias, +mask)
    dim3 g2(N_ / 64, H_, B_);              // 32 x 16 x 2
    attn_kernel<<<g2, 256>>>(attn_bias, key_padding_mask);

    // 3) Output projection
    void* pAO = nullptr;
    cudaGetSymbolAddress(&pAO, g_AO);
    dim3 g3(DIM_ / 128, (B_ * N_) / 128);  // 8 x 32
    sgemm_kernel<0><<<g3, 256>>>((const float*)pAO, proj_w, proj_b, out,
                                 B_ * N_, DIM_, DIM_);
}

// round 2
// speedup vs baseline: 2.0942x; 2.0942x over previous
#include <cuda_runtime.h>

#define B_    2
#define N_    2048
#define DIM_  1024
#define H_    16
#define D_    64
#define E3_   3072
#define SCALE_ 0.125f

// Scratch (no allocations allowed)
__device__ float g_Q[B_ * H_ * N_ * D_];
__device__ float g_K[B_ * H_ * N_ * D_];
__device__ float g_V[B_ * H_ * N_ * D_];
__device__ float g_AO[B_ * N_ * DIM_];

__device__ __forceinline__ unsigned f2tf(float f) {
    unsigned u;
    asm("cvt.rna.tf32.f32 %0, %1;" : "=r"(u) : "f"(f));
    return u;
}

__device__ __forceinline__ void mma_tf32(float c[4], const unsigned a[4], const unsigned b[2]) {
    asm volatile(
        "mma.sync.aligned.m16n8k8.row.col.f32.tf32.tf32.f32 "
        "{%0,%1,%2,%3},{%4,%5,%6,%7},{%8,%9},{%0,%1,%2,%3};"
        : "+f"(c[0]), "+f"(c[1]), "+f"(c[2]), "+f"(c[3])
        : "r"(a[0]), "r"(a[1]), "r"(a[2]), "r"(a[3]), "r"(b[0]), "r"(b[1]));
}

// ---------------------------------------------------------------------------
// tf32 GEMM: C[M,Nn] = A[M,K] @ W[Nn,K]^T + bias
// MODE 0: plain write. MODE 1: QKV scatter to g_Q (scaled)/g_K/g_V.
// Block 128x128, k-chunk 16, 256 threads = 8 warps of 64x32.
// smem layout [row][k] pad 20 -> conflict-free mma fragment LDS.
// ---------------------------------------------------------------------------
template <int MODE>
__global__ __launch_bounds__(256) void tgemm(
    const float* __restrict__ A, const float* __restrict__ W,
    const float* __restrict__ bias, float* __restrict__ C,
    int M, int Nn, int K)
{
    __shared__ unsigned As[128][20];
    __shared__ unsigned Bs[128][20];

    const int tid = threadIdx.x;
    const int bm = blockIdx.y * 128, bn = blockIdx.x * 128;
    const int w = tid >> 5, lane = tid & 31;
    const int gid = lane >> 2, tig = lane & 3;
    const int wm = (w & 1) * 64, wn = (w >> 1) * 32;
    const int lr = tid >> 2, lc = (tid & 3) << 2;   // load mapping: row lr/lr+64, k cols lc..lc+3

    float acc[4][4][4];
#pragma unroll
    for (int mt = 0; mt < 4; mt++)
#pragma unroll
        for (int nt = 0; nt < 4; nt++)
#pragma unroll
            for (int i = 0; i < 4; i++) acc[mt][nt][i] = 0.f;

    const float* Ap0 = A + (size_t)(bm + lr) * K + lc;
    const float* Ap1 = A + (size_t)(bm + lr + 64) * K + lc;
    const float* Wp0 = W + (size_t)(bn + lr) * K + lc;
    const float* Wp1 = W + (size_t)(bn + lr + 64) * K + lc;

    float4 va0 = *(const float4*)Ap0;
    float4 va1 = *(const float4*)Ap1;
    float4 vb0 = *(const float4*)Wp0;
    float4 vb1 = *(const float4*)Wp1;

    for (int k0 = 0; k0 < K; k0 += 16) {
        As[lr][lc + 0] = f2tf(va0.x); As[lr][lc + 1] = f2tf(va0.y);
        As[lr][lc + 2] = f2tf(va0.z); As[lr][lc + 3] = f2tf(va0.w);
        As[lr + 64][lc + 0] = f2tf(va1.x); As[lr + 64][lc + 1] = f2tf(va1.y);
        As[lr + 64][lc + 2] = f2tf(va1.z); As[lr + 64][lc + 3] = f2tf(va1.w);
        Bs[lr][lc + 0] = f2tf(vb0.x); Bs[lr][lc + 1] = f2tf(vb0.y);
        Bs[lr][lc + 2] = f2tf(vb0.z); Bs[lr][lc + 3] = f2tf(vb0.w);
        Bs[lr + 64][lc + 0] = f2tf(vb1.x); Bs[lr + 64][lc + 1] = f2tf(vb1.y);
        Bs[lr + 64][lc + 2] = f2tf(vb1.z); Bs[lr + 64][lc + 3] = f2tf(vb1.w);
        __syncthreads();

        if (k0 + 16 < K) {   // prefetch next chunk into registers during mma
            va0 = *(const float4*)(Ap0 + k0 + 16);
            va1 = *(const float4*)(Ap1 + k0 + 16);
            vb0 = *(const float4*)(Wp0 + k0 + 16);
            vb1 = *(const float4*)(Wp1 + k0 + 16);
        }

#pragma unroll
        for (int ks = 0; ks < 16; ks += 8) {
            unsigned af[4][4], bf[4][2];
#pragma unroll
            for (int mt = 0; mt < 4; mt++) {
                int m = wm + mt * 16;
                af[mt][0] = As[m + gid][ks + tig];
                af[mt][1] = As[m + gid + 8][ks + tig];
                af[mt][2] = As[m + gid][ks + tig + 4];
                af[mt][3] = As[m + gid + 8][ks + tig + 4];
            }
#pragma unroll
            for (int nt = 0; nt < 4; nt++) {
                int n = wn + nt * 8;
                bf[nt][0] = Bs[n + gid][ks + tig];
                bf[nt][1] = Bs[n + gid][ks + tig + 4];
            }
#pragma unroll
            for (int mt = 0; mt < 4; mt++)
#pragma unroll
                for (int nt = 0; nt < 4; nt++)
                    mma_tf32(acc[mt][nt], af[mt], bf[nt]);
        }
        __syncthreads();
    }

    // Epilogue. c0:(gid,2t) c1:(gid,2t+1) c2:(gid+8,2t) c3:(gid+8,2t+1)
#pragma unroll
    for (int mt = 0; mt < 4; mt++) {
#pragma unroll
        for (int nt = 0; nt < 4; nt++) {
            int r0 = bm + wm + mt * 16 + gid;
            int c0 = bn + wn + nt * 8 + 2 * tig;
            float v00 = acc[mt][nt][0] + bias[c0];
            float v01 = acc[mt][nt][1] + bias[c0 + 1];
            float v10 = acc[mt][nt][2] + bias[c0];
            float v11 = acc[mt][nt][3] + bias[c0 + 1];
            if (MODE == 0) {
                C[(size_t)r0 * Nn + c0]       = v00;
                C[(size_t)r0 * Nn + c0 + 1]   = v01;
                C[(size_t)(r0 + 8) * Nn + c0]     = v10;
                C[(size_t)(r0 + 8) * Nn + c0 + 1] = v11;
            } else {
#pragma unroll
                for (int p = 0; p < 4; p++) {
                    int m = (p < 2) ? r0 : (r0 + 8);
                    int e = c0 + (p & 1);
                    float v = (p == 0) ? v00 : (p == 1) ? v01 : (p == 2) ? v10 : v11;
                    int bb = m >> 11;
                    int n = m & 2047;
                    int which = e >> 10;
                    int hh = (e >> 6) & 15;
                    int d = e & 63;
                    size_t idx = ((size_t)(bb * H_ + hh) * N_ + n) * D_ + d;
                    if (which == 0)      g_Q[idx] = v * SCALE_;
                    else if (which == 1) g_K[idx] = v;
                    else                 g_V[idx] = v;
                }
            }
        }
    }
}

// ---------------------------------------------------------------------------
// Attention: block = (b, h, 64 q rows), kv tiles of 64, tf32 mma for QK^T and
// P@V, online softmax. 8 warps, warp = 16 q-rows x 32 cols.
// ---------------------------------------------------------------------------
__global__ __launch_bounds__(256) void attn_kernel(
    const float* __restrict__ bias, const unsigned char* __restrict__ mask)
{
    extern __shared__ char smraw[];
    unsigned* Qs = (unsigned*)smraw;           // [64][68]
    unsigned* Ks = Qs + 64 * 68;               // [64][68]
    float*    Ss = (float*)(Ks + 64 * 68);     // [64][68]
    unsigned* Vs = (unsigned*)(Ss + 64 * 68);  // [64][72]
    float* mrow = (float*)(Vs + 64 * 72);
    float* lrow = mrow + 64;
    float* arow = lrow + 64;

    const int tid = threadIdx.x;
    const int b = blockIdx.z, h = blockIdx.y, q0 = blockIdx.x * 64;
    const int w = tid >> 5, lane = tid & 31;
    const int gid = lane >> 2, tig = lane & 3;
    const int wqm = (w >> 1) * 16, wqn = (w & 1) * 32;
    const int sr = tid >> 2, sseg = tid & 3;

    const float* Qg = g_Q + (size_t)(b * H_ + h) * N_ * D_;
    const float* Kg = g_K + (size_t)(b * H_ + h) * N_ * D_;
    const float* Vg = g_V + (size_t)(b * H_ + h) * N_ * D_;
    const float* biash = bias + (size_t)h * N_ * N_;
    const unsigned char* maskb = mask + (size_t)b * N_;

    // Load Q tile (64x64), convert to tf32
    {
        int r = tid >> 2, c = (tid & 3) * 16;
        const float* src = Qg + (size_t)(q0 + r) * D_ + c;
#pragma unroll
        for (int t = 0; t < 4; t++) {
            float4 v = *(const float4*)(src + t * 4);
            Qs[r * 68 + c + t * 4 + 0] = f2tf(v.x);
            Qs[r * 68 + c + t * 4 + 1] = f2tf(v.y);
            Qs[r * 68 + c + t * 4 + 2] = f2tf(v.z);
            Qs[r * 68 + c + t * 4 + 3] = f2tf(v.w);
        }
    }
    if (tid < 64) { mrow[tid] = -1e30f; lrow[tid] = 0.f; }

    float o[4][4];
#pragma unroll
    for (int nt = 0; nt < 4; nt++)
#pragma unroll
        for (int i = 0; i < 4; i++) o[nt][i] = 0.f;

    __syncthreads();

    for (int kt = 0; kt < N_; kt += 64) {
        // Load K,V tiles (64x64 each)
        {
            int r = tid >> 2, c = (tid & 3) * 16;
            const float* ksrc = Kg + (size_t)(kt + r) * D_ + c;
            const float* vsrc = Vg + (size_t)(kt + r) * D_ + c;
#pragma unroll
            for (int t = 0; t < 4; t++) {
                float4 vk = *(const float4*)(ksrc + t * 4);
                Ks[r * 68 + c + t * 4 + 0] = f2tf(vk.x);
                Ks[r * 68 + c + t * 4 + 1] = f2tf(vk.y);
                Ks[r * 68 + c + t * 4 + 2] = f2tf(vk.z);
                Ks[r * 68 + c + t * 4 + 3] = f2tf(vk.w);
                float4 vv = *(const float4*)(vsrc + t * 4);
                Vs[r * 72 + c + t * 4 + 0] = f2tf(vv.x);
                Vs[r * 72 + c + t * 4 + 1] = f2tf(vv.y);
                Vs[r * 72 + c + t * 4 + 2] = f2tf(vv.z);
                Vs[r * 72 + c + t * 4 + 3] = f2tf(vv.w);
            }
        }
        __syncthreads();

        // S = Q @ K^T (Q pre-scaled)
        float s[4][4];
#pragma unroll
        for (int nt = 0; nt < 4; nt++)
#pragma unroll
            for (int i = 0; i < 4; i++) s[nt][i] = 0.f;

#pragma unroll
        for (int ks = 0; ks < 64; ks += 8) {
            unsigned a[4];
            a[0] = Qs[(wqm + gid) * 68 + ks + tig];
            a[1] = Qs[(wqm + gid + 8) * 68 + ks + tig];
            a[2] = Qs[(wqm + gid) * 68 + ks + tig + 4];
            a[3] = Qs[(wqm + gid + 8) * 68 + ks + tig + 4];
#pragma unroll
            for (int nt = 0; nt < 4; nt++) {
                unsigned bb[2];
                bb[0] = Ks[(wqn + nt * 8 + gid) * 68 + ks + tig];
                bb[1] = Ks[(wqn + nt * 8 + gid) * 68 + ks + tig + 4];
                mma_tf32(s[nt], a, bb);
            }
        }

        // bias + mask, write logits to Ss (fp32)
#pragma unroll
        for (int nt = 0; nt < 4; nt++) {
            int r0 = wqm + gid, c0 = wqn + nt * 8 + 2 * tig;
            float2 bz0 = *(const float2*)(biash + (size_t)(q0 + r0) * N_ + kt + c0);
            float2 bz1 = *(const float2*)(biash + (size_t)(q0 + r0 + 8) * N_ + kt + c0);
            float v00 = s[nt][0] + bz0.x;
            float v01 = s[nt][1] + bz0.y;
            float v10 = s[nt][2] + bz1.x;
            float v11 = s[nt][3] + bz1.y;
            if (maskb[kt + c0])     { v00 = -1e30f; v10 = -1e30f; }
            if (maskb[kt + c0 + 1]) { v01 = -1e30f; v11 = -1e30f; }
            Ss[r0 * 68 + c0] = v00;       Ss[r0 * 68 + c0 + 1] = v01;
            Ss[(r0 + 8) * 68 + c0] = v10; Ss[(r0 + 8) * 68 + c0 + 1] = v11;
        }
        __syncthreads();

        // row max (4 lanes per row, 16 cols each)
        {
            float tm = -1e30f;
            int base = sr * 68 + sseg * 16;
#pragma unroll
            for (int j = 0; j < 16; j++) tm = fmaxf(tm, Ss[base + j]);
            tm = fmaxf(tm, __shfl_xor_sync(0xffffffffu, tm, 1));
            tm = fmaxf(tm, __shfl_xor_sync(0xffffffffu, tm, 2));
            if (sseg == 0) {
                float mo = mrow[sr];
                float mn = fmaxf(mo, tm);
                arow[sr] = __expf(mo - mn);
                mrow[sr] = mn;
            }
        }
        __syncthreads();

        // exp + tf32 round + row sum
        {
            float mn = mrow[sr];
            float ps = 0.f;
            int base = sr * 68 + sseg * 16;
#pragma unroll
            for (int j = 0; j < 16; j++) {
                float e = __expf(Ss[base + j] - mn);
                unsigned et = f2tf(e);
                ps += __uint_as_float(et);
                Ss[base + j] = __uint_as_float(et);
            }
            ps += __shfl_xor_sync(0xffffffffu, ps, 1);
            ps += __shfl_xor_sync(0xffffffffu, ps, 2);
            if (sseg == 0) lrow[sr] = lrow[sr] * arow[sr] + ps;
        }
        __syncthreads();

        // rescale O, then O += P @ V
        {
            float al0 = arow[wqm + gid], al1 = arow[wqm + gid + 8];
#pragma unroll
            for (int nt = 0; nt < 4; nt++) {
                o[nt][0] *= al0; o[nt][1] *= al0;
                o[nt][2] *= al1; o[nt][3] *= al1;
            }
        }
#pragma unroll
        for (int ks = 0; ks < 64; ks += 8) {
            unsigned a[4];
            a[0] = __float_as_uint(Ss[(wqm + gid) * 68 + ks + tig]);
            a[1] = __float_as_uint(Ss[(wqm + gid + 8) * 68 + ks + tig]);
            a[2] = __float_as_uint(Ss[(wqm + gid) * 68 + ks + tig + 4]);
            a[3] = __float_as_uint(Ss[(wqm + gid + 8) * 68 + ks + tig + 4]);
#pragma unroll
            for (int nt = 0; nt < 4; nt++) {
                unsigned bb[2];
                bb[0] = Vs[(ks + tig) * 72 + wqn + nt * 8 + gid];
                bb[1] = Vs[(ks + tig + 4) * 72 + wqn + nt * 8 + gid];
                mma_tf32(o[nt], a, bb);
            }
        }
        __syncthreads();
    }

    // Epilogue: normalize and write [b, n, h*64 + d]
    {
        float inv0 = 1.f / lrow[wqm + gid];
        float inv1 = 1.f / lrow[wqm + gid + 8];
#pragma unroll
        for (int nt = 0; nt < 4; nt++) {
            int r0 = q0 + wqm + gid;
            int c0 = h * D_ + wqn + nt * 8 + 2 * tig;
            float* dst0 = g_AO + (size_t)(b * N_ + r0) * DIM_ + c0;
            float* dst1 = g_AO + (size_t)(b * N_ + r0 + 8) * DIM_ + c0;
            dst0[0] = o[nt][0] * inv0; dst0[1] = o[nt][1] * inv0;
            dst1[0] = o[nt][2] * inv1; dst1[1] = o[nt][3] * inv1;
        }
    }
}

// ---------------------------------------------------------------------------
extern "C" void kernel_launch(void* const* d_in, const int* in_sizes, int n_in,
                              void* d_out, int out_size)
{
    (void)in_sizes; (void)n_in; (void)out_size;
    const float* x         = (const float*)d_in[0];
    const float* attn_bias = (const float*)d_in[1];
    const unsigned char* key_padding_mask = (const unsigned char*)d_in[2];
    const float* qkv_w     = (const float*)d_in[3];
    const float* qkv_b     = (const float*)d_in[4];
    const float* proj_w    = (const float*)d_in[5];
    const float* proj_b    = (const float*)d_in[6];
    float* out = (float*)d_out;

    const int ATTN_SMEM = (64 * 68 * 3 + 64 * 72 + 192) * 4;  // 71424 B
    cudaFuncSetAttribute(attn_kernel, cudaFuncAttributeMaxDynamicSharedMemorySize, ATTN_SMEM);

    dim3 g1(E3_ / 128, (B_ * N_) / 128);   // 24 x 32
    tgemm<1><<<g1, 256>>>(x, qkv_w, qkv_b, nullptr, B_ * N_, E3_, DIM_);

    dim3 g2(N_ / 64, H_, B_);              // 32 x 16 x 2
    attn_kernel<<<g2, 256, ATTN_SMEM>>>(attn_bias, key_padding_mask);

    void* pAO = nullptr;
    cudaGetSymbolAddress(&pAO, g_AO);
    dim3 g3(DIM_ / 128, (B_ * N_) / 128);  // 8 x 32
    tgemm<0><<<g3, 256>>>((const float*)pAO, proj_w, proj_b, out,
                          B_ * N_, DIM_, DIM_);
}

// round 3
// speedup vs baseline: 2.6172x; 1.2497x over previous
#include <cuda_runtime.h>

#define B_    2
#define N_    2048
#define DIM_  1024
#define H_    16
#define D_    64
#define E3_   3072
#define SCALE_ 0.125f

// Scratch (no allocations allowed)
__device__ float g_Q[B_ * H_ * N_ * D_];
__device__ float g_K[B_ * H_ * N_ * D_];
__device__ float g_V[B_ * H_ * N_ * D_];
__device__ float g_AO[B_ * N_ * DIM_];

__device__ __forceinline__ unsigned f2tf(float f) {
    unsigned u;
    asm("cvt.rna.tf32.f32 %0, %1;" : "=r"(u) : "f"(f));
    return u;
}

__device__ __forceinline__ void mma_tf32(float c[4], const unsigned a[4], const unsigned b[2]) {
    asm volatile(
        "mma.sync.aligned.m16n8k8.row.col.f32.tf32.tf32.f32 "
        "{%0,%1,%2,%3},{%4,%5,%6,%7},{%8,%9},{%0,%1,%2,%3};"
        : "+f"(c[0]), "+f"(c[1]), "+f"(c[2]), "+f"(c[3])
        : "r"(a[0]), "r"(a[1]), "r"(a[2]), "r"(a[3]), "r"(b[0]), "r"(b[1]));
}

// ---------------------------------------------------------------------------
// tf32 GEMM: C = A[M,K] @ W[Nn,K]^T + bias. Double-buffered smem, 1 sync/chunk.
// MODE 0: plain write. MODE 1: QKV scatter to g_Q(scaled)/g_K/g_V.
// ---------------------------------------------------------------------------
template <int MODE>
__global__ __launch_bounds__(256, 2) void tgemm(
    const float* __restrict__ A, const float* __restrict__ W,
    const float* __restrict__ bias, float* __restrict__ C,
    int M, int Nn, int K)
{
    __shared__ unsigned As[2][128][20];
    __shared__ unsigned Bs[2][128][20];

    const int tid = threadIdx.x;
    const int bm = blockIdx.y * 128, bn = blockIdx.x * 128;
    const int w = tid >> 5, lane = tid & 31;
    const int gid = lane >> 2, tig = lane & 3;
    const int wm = (w & 1) * 64, wn = (w >> 1) * 32;
    const int lr = tid >> 2, lc = (tid & 3) << 2;

    float acc[4][4][4];
#pragma unroll
    for (int mt = 0; mt < 4; mt++)
#pragma unroll
        for (int nt = 0; nt < 4; nt++)
#pragma unroll
            for (int i = 0; i < 4; i++) acc[mt][nt][i] = 0.f;

    const float* Ap0 = A + (size_t)(bm + lr) * K + lc;
    const float* Ap1 = A + (size_t)(bm + lr + 64) * K + lc;
    const float* Wp0 = W + (size_t)(bn + lr) * K + lc;
    const float* Wp1 = W + (size_t)(bn + lr + 64) * K + lc;

    float4 va0 = *(const float4*)Ap0;
    float4 va1 = *(const float4*)Ap1;
    float4 vb0 = *(const float4*)Wp0;
    float4 vb1 = *(const float4*)Wp1;

    // store chunk 0 -> stage 0
    {
        uint4 u;
        u.x = f2tf(va0.x); u.y = f2tf(va0.y); u.z = f2tf(va0.z); u.w = f2tf(va0.w);
        *(uint4*)&As[0][lr][lc] = u;
        u.x = f2tf(va1.x); u.y = f2tf(va1.y); u.z = f2tf(va1.z); u.w = f2tf(va1.w);
        *(uint4*)&As[0][lr + 64][lc] = u;
        u.x = f2tf(vb0.x); u.y = f2tf(vb0.y); u.z = f2tf(vb0.z); u.w = f2tf(vb0.w);
        *(uint4*)&Bs[0][lr][lc] = u;
        u.x = f2tf(vb1.x); u.y = f2tf(vb1.y); u.z = f2tf(vb1.z); u.w = f2tf(vb1.w);
        *(uint4*)&Bs[0][lr + 64][lc] = u;
    }
    __syncthreads();

    const int NC = K >> 4;
    for (int c = 0; c < NC; c++) {
        const int cur = c & 1;
        if (c + 1 < NC) {
            va0 = *(const float4*)(Ap0 + (c + 1) * 16);
            va1 = *(const float4*)(Ap1 + (c + 1) * 16);
            vb0 = *(const float4*)(Wp0 + (c + 1) * 16);
            vb1 = *(const float4*)(Wp1 + (c + 1) * 16);
        }
#pragma unroll
        for (int ks = 0; ks < 16; ks += 8) {
            unsigned af[4][4], bf[4][2];
#pragma unroll
            for (int mt = 0; mt < 4; mt++) {
                int m = wm + mt * 16;
                af[mt][0] = As[cur][m + gid][ks + tig];
                af[mt][1] = As[cur][m + gid + 8][ks + tig];
                af[mt][2] = As[cur][m + gid][ks + tig + 4];
                af[mt][3] = As[cur][m + gid + 8][ks + tig + 4];
            }
#pragma unroll
            for (int nt = 0; nt < 4; nt++) {
                int n = wn + nt * 8;
                bf[nt][0] = Bs[cur][n + gid][ks + tig];
                bf[nt][1] = Bs[cur][n + gid][ks + tig + 4];
            }
#pragma unroll
            for (int mt = 0; mt < 4; mt++)
#pragma unroll
                for (int nt = 0; nt < 4; nt++)
                    mma_tf32(acc[mt][nt], af[mt], bf[nt]);
        }
        if (c + 1 < NC) {
            const int nxt = cur ^ 1;
            uint4 u;
            u.x = f2tf(va0.x); u.y = f2tf(va0.y); u.z = f2tf(va0.z); u.w = f2tf(va0.w);
            *(uint4*)&As[nxt][lr][lc] = u;
            u.x = f2tf(va1.x); u.y = f2tf(va1.y); u.z = f2tf(va1.z); u.w = f2tf(va1.w);
            *(uint4*)&As[nxt][lr + 64][lc] = u;
            u.x = f2tf(vb0.x); u.y = f2tf(vb0.y); u.z = f2tf(vb0.z); u.w = f2tf(vb0.w);
            *(uint4*)&Bs[nxt][lr][lc] = u;
            u.x = f2tf(vb1.x); u.y = f2tf(vb1.y); u.z = f2tf(vb1.z); u.w = f2tf(vb1.w);
            *(uint4*)&Bs[nxt][lr + 64][lc] = u;
        }
        __syncthreads();
    }

#pragma unroll
    for (int mt = 0; mt < 4; mt++) {
#pragma unroll
        for (int nt = 0; nt < 4; nt++) {
            int r0 = bm + wm + mt * 16 + gid;
            int c0 = bn + wn + nt * 8 + 2 * tig;
            float v00 = acc[mt][nt][0] + bias[c0];
            float v01 = acc[mt][nt][1] + bias[c0 + 1];
            float v10 = acc[mt][nt][2] + bias[c0];
            float v11 = acc[mt][nt][3] + bias[c0 + 1];
            if (MODE == 0) {
                C[(size_t)r0 * Nn + c0]           = v00;
                C[(size_t)r0 * Nn + c0 + 1]       = v01;
                C[(size_t)(r0 + 8) * Nn + c0]     = v10;
                C[(size_t)(r0 + 8) * Nn + c0 + 1] = v11;
            } else {
#pragma unroll
                for (int p = 0; p < 4; p++) {
                    int m = (p < 2) ? r0 : (r0 + 8);
                    int e = c0 + (p & 1);
                    float v = (p == 0) ? v00 : (p == 1) ? v01 : (p == 2) ? v10 : v11;
                    int bb = m >> 11;
                    int n = m & 2047;
                    int which = e >> 10;
                    int hh = (e >> 6) & 15;
                    int d = e & 63;
                    size_t idx = ((size_t)(bb * H_ + hh) * N_ + n) * D_ + d;
                    if (which == 0)      g_Q[idx] = v * SCALE_;
                    else if (which == 1) g_K[idx] = v;
                    else                 g_V[idx] = v;
                }
            }
        }
    }
}

// ---------------------------------------------------------------------------
// Attention: block = 128 q rows x (b,h). 8 warps, each warp = 16 q x 64 kv.
// Register-resident S/softmax (quad shuffles), K/V double-buffered in smem,
// ONE syncthreads per kv tile. Q fragment register-resident (loaded once).
// ---------------------------------------------------------------------------
__global__ __launch_bounds__(256, 1) void attn_kernel(
    const float* __restrict__ bias, const unsigned char* __restrict__ mask)
{
    extern __shared__ unsigned smu[];
    // K: [2][64][68], V: [2][64][72]
#define KS(st, r, c) smu[(st) * (64 * 68) + (r) * 68 + (c)]
#define VS(st, r, c) smu[2 * 64 * 68 + (st) * (64 * 72) + (r) * 72 + (c)]

    const int tid = threadIdx.x;
    const int w = tid >> 5, lane = tid & 31;
    const int gid = lane >> 2, tig = lane & 3;
    const int b = blockIdx.x, q0 = blockIdx.y * 128, h = blockIdx.z;
    const int qr = q0 + w * 16 + gid;

    const size_t bh = (size_t)(b * H_ + h) * N_ * D_;
    const float* Qg = g_Q + bh;
    const float* Kg = g_K + bh;
    const float* Vg = g_V + bh;
    const float* brow0 = bias + (size_t)h * N_ * N_ + (size_t)qr * N_;
    const float* brow1 = brow0 + 8 * N_;
    const unsigned char* maskb = mask + (size_t)b * N_;

    // Q fragments (register resident for whole kernel)
    unsigned qf[8][4];
#pragma unroll
    for (int kc = 0; kc < 8; kc++) {
        qf[kc][0] = f2tf(Qg[(size_t)qr * D_ + kc * 8 + tig]);
        qf[kc][1] = f2tf(Qg[(size_t)(qr + 8) * D_ + kc * 8 + tig]);
        qf[kc][2] = f2tf(Qg[(size_t)qr * D_ + kc * 8 + tig + 4]);
        qf[kc][3] = f2tf(Qg[(size_t)(qr + 8) * D_ + kc * 8 + tig + 4]);
    }

    const int r_ld = tid >> 2, c_ld = (tid & 3) * 16;
    float4 pk[4], pv[4];
#pragma unroll
    for (int t = 0; t < 4; t++) {
        pk[t] = *(const float4*)(Kg + (size_t)r_ld * D_ + c_ld + t * 4);
        pv[t] = *(const float4*)(Vg + (size_t)r_ld * D_ + c_ld + t * 4);
    }
#pragma unroll
    for (int t = 0; t < 4; t++) {
        uint4 u;
        u.x = f2tf(pk[t].x); u.y = f2tf(pk[t].y); u.z = f2tf(pk[t].z); u.w = f2tf(pk[t].w);
        *(uint4*)&KS(0, r_ld, c_ld + t * 4) = u;
        u.x = f2tf(pv[t].x); u.y = f2tf(pv[t].y); u.z = f2tf(pv[t].z); u.w = f2tf(pv[t].w);
        *(uint4*)&VS(0, r_ld, c_ld + t * 4) = u;
    }
    __syncthreads();

    float m0 = -1e30f, m1 = -1e30f, l0 = 0.f, l1 = 0.f;
    float o[8][4];
#pragma unroll
    for (int nt = 0; nt < 8; nt++)
#pragma unroll
        for (int i = 0; i < 4; i++) o[nt][i] = 0.f;

    const int NT = N_ / 64;
    for (int kti = 0; kti < NT; kti++) {
        const int cur = kti & 1;
        const int kt = kti * 64;

        if (kti + 1 < NT) {
            const float* Kn = Kg + (size_t)(kt + 64 + r_ld) * D_ + c_ld;
            const float* Vn = Vg + (size_t)(kt + 64 + r_ld) * D_ + c_ld;
#pragma unroll
            for (int t = 0; t < 4; t++) {
                pk[t] = *(const float4*)(Kn + t * 4);
                pv[t] = *(const float4*)(Vn + t * 4);
            }
        }

        // S = Q @ K^T + bias (+mask)
        float s[8][4];
#pragma unroll
        for (int nt = 0; nt < 8; nt++) {
            const int colc = nt * 8 + 2 * tig;
            float2 bz0 = *(const float2*)(brow0 + kt + colc);
            float2 bz1 = *(const float2*)(brow1 + kt + colc);
            uchar2 mk = *(const uchar2*)(maskb + kt + colc);
            float sr[4] = {0.f, 0.f, 0.f, 0.f};
#pragma unroll
            for (int kc = 0; kc < 8; kc++) {
                unsigned bb[2];
                bb[0] = KS(cur, nt * 8 + gid, kc * 8 + tig);
                bb[1] = KS(cur, nt * 8 + gid, kc * 8 + tig + 4);
                mma_tf32(sr, qf[kc], bb);
            }
            sr[0] += bz0.x; sr[1] += bz0.y; sr[2] += bz1.x; sr[3] += bz1.y;
            if (mk.x) { sr[0] = -1e30f; sr[2] = -1e30f; }
            if (mk.y) { sr[1] = -1e30f; sr[3] = -1e30f; }
            s[nt][0] = sr[0]; s[nt][1] = sr[1]; s[nt][2] = sr[2]; s[nt][3] = sr[3];
        }

        // row max over quad
        float tm0 = -1e30f, tm1 = -1e30f;
#pragma unroll
        for (int nt = 0; nt < 8; nt++) {
            tm0 = fmaxf(tm0, fmaxf(s[nt][0], s[nt][1]));
            tm1 = fmaxf(tm1, fmaxf(s[nt][2], s[nt][3]));
        }
        tm0 = fmaxf(tm0, __shfl_xor_sync(0xffffffffu, tm0, 1));
        tm0 = fmaxf(tm0, __shfl_xor_sync(0xffffffffu, tm0, 2));
        tm1 = fmaxf(tm1, __shfl_xor_sync(0xffffffffu, tm1, 1));
        tm1 = fmaxf(tm1, __shfl_xor_sync(0xffffffffu, tm1, 2));

        const float mn0 = fmaxf(m0, tm0), mn1 = fmaxf(m1, tm1);
        const float al0 = __expf(m0 - mn0), al1 = __expf(m1 - mn1);
        m0 = mn0; m1 = mn1;

        float ps0 = 0.f, ps1 = 0.f;
#pragma unroll
        for (int nt = 0; nt < 8; nt++) {
            float p0 = __uint_as_float(f2tf(__expf(s[nt][0] - mn0)));
            float p1 = __uint_as_float(f2tf(__expf(s[nt][1] - mn0)));
            float p2 = __uint_as_float(f2tf(__expf(s[nt][2] - mn1)));
            float p3 = __uint_as_float(f2tf(__expf(s[nt][3] - mn1)));
            ps0 += p0 + p1; ps1 += p2 + p3;
            s[nt][0] = p0; s[nt][1] = p1; s[nt][2] = p2; s[nt][3] = p3;
        }
        ps0 += __shfl_xor_sync(0xffffffffu, ps0, 1);
        ps0 += __shfl_xor_sync(0xffffffffu, ps0, 2);
        ps1 += __shfl_xor_sync(0xffffffffu, ps1, 1);
        ps1 += __shfl_xor_sync(0xffffffffu, ps1, 2);
        l0 = l0 * al0 + ps0;
        l1 = l1 * al1 + ps1;

#pragma unroll
        for (int nt = 0; nt < 8; nt++) {
            o[nt][0] *= al0; o[nt][1] *= al0;
            o[nt][2] *= al1; o[nt][3] *= al1;
        }

        // O += P @ V  (remap C-frag -> A-frag via quad shuffles)
        const int src1 = (lane & ~3) | (tig >> 1);
        const int src2 = src1 + 2;
#pragma unroll
        for (int kc = 0; kc < 8; kc++) {
            float e00 = __shfl_sync(0xffffffffu, s[kc][0], src1);
            float e01 = __shfl_sync(0xffffffffu, s[kc][1], src1);
            float e20 = __shfl_sync(0xffffffffu, s[kc][2], src1);
            float e21 = __shfl_sync(0xffffffffu, s[kc][3], src1);
            float f00 = __shfl_sync(0xffffffffu, s[kc][0], src2);
            float f01 = __shfl_sync(0xffffffffu, s[kc][1], src2);
            float f20 = __shfl_sync(0xffffffffu, s[kc][2], src2);
            float f21 = __shfl_sync(0xffffffffu, s[kc][3], src2);
            unsigned a[4];
            a[0] = __float_as_uint((tig & 1) ? e01 : e00);
            a[1] = __float_as_uint((tig & 1) ? e21 : e20);
            a[2] = __float_as_uint((tig & 1) ? f01 : f00);
            a[3] = __float_as_uint((tig & 1) ? f21 : f20);
#pragma unroll
            for (int nt = 0; nt < 8; nt++) {
                unsigned bb[2];
                bb[0] = VS(cur, kc * 8 + tig, nt * 8 + gid);
                bb[1] = VS(cur, kc * 8 + tig + 4, nt * 8 + gid);
                mma_tf32(o[nt], a, bb);
            }
        }

        if (kti + 1 < NT) {
            const int nxt = cur ^ 1;
#pragma unroll
            for (int t = 0; t < 4; t++) {
                uint4 u;
                u.x = f2tf(pk[t].x); u.y = f2tf(pk[t].y); u.z = f2tf(pk[t].z); u.w = f2tf(pk[t].w);
                *(uint4*)&KS(nxt, r_ld, c_ld + t * 4) = u;
                u.x = f2tf(pv[t].x); u.y = f2tf(pv[t].y); u.z = f2tf(pv[t].z); u.w = f2tf(pv[t].w);
                *(uint4*)&VS(nxt, r_ld, c_ld + t * 4) = u;
            }
        }
        __syncthreads();
    }

    // epilogue
    const float inv0 = 1.f / l0, inv1 = 1.f / l1;
    float* dst0 = g_AO + (size_t)(b * N_ + qr) * DIM_ + h * D_;
    float* dst1 = dst0 + 8 * DIM_;
#pragma unroll
    for (int nt = 0; nt < 8; nt++) {
        int cc = nt * 8 + 2 * tig;
        float2 v0 = make_float2(o[nt][0] * inv0, o[nt][1] * inv0);
        float2 v1 = make_float2(o[nt][2] * inv1, o[nt][3] * inv1);
        *(float2*)(dst0 + cc) = v0;
        *(float2*)(dst1 + cc) = v1;
    }
#undef KS
#undef VS
}

// ---------------------------------------------------------------------------
extern "C" void kernel_launch(void* const* d_in, const int* in_sizes, int n_in,
                              void* d_out, int out_size)
{
    (void)in_sizes; (void)n_in; (void)out_size;
    const float* x         = (const float*)d_in[0];
    const float* attn_bias = (const float*)d_in[1];
    const unsigned char* key_padding_mask = (const unsigned char*)d_in[2];
    const float* qkv_w     = (const float*)d_in[3];
    const float* qkv_b     = (const float*)d_in[4];
    const float* proj_w    = (const float*)d_in[5];
    const float* proj_b    = (const float*)d_in[6];
    float* out = (float*)d_out;

    const int ATTN_SMEM = (2 * 64 * 68 + 2 * 64 * 72) * 4;  // 71680 B
    cudaFuncSetAttribute(attn_kernel, cudaFuncAttributeMaxDynamicSharedMemorySize, ATTN_SMEM);

    dim3 g1(E3_ / 128, (B_ * N_) / 128);   // 24 x 32
    tgemm<1><<<g1, 256>>>(x, qkv_w, qkv_b, nullptr, B_ * N_, E3_, DIM_);

    dim3 g2(B_, N_ / 128, H_);             // 2 x 16 x 16
    attn_kernel<<<g2, 256, ATTN_SMEM>>>(attn_bias, key_padding_mask);

    void* pAO = nullptr;
    cudaGetSymbolAddress(&pAO, g_AO);
    dim3 g3(DIM_ / 128, (B_ * N_) / 128);  // 8 x 32
    tgemm<0><<<g3, 256>>>((const float*)pAO, proj_w, proj_b, out,
                          B_ * N_, DIM_, DIM_);
}

// round 4
// speedup vs baseline: 2.8760x; 1.0989x over previous
#include <cuda_runtime.h>

#define B_    2
#define N_    2048
#define DIM_  1024
#define H_    16
#define D_    64
#define E3_   3072
#define SCALE_ 0.125f

// Scratch (no allocations allowed)
__device__ float g_Q[B_ * H_ * N_ * D_];
__device__ float g_K[B_ * H_ * N_ * D_];
__device__ float g_V[B_ * H_ * N_ * D_];
__device__ float g_AO[B_ * N_ * DIM_];

__device__ __forceinline__ unsigned f2tf(float f) {
    unsigned u;
    asm("cvt.rna.tf32.f32 %0, %1;" : "=r"(u) : "f"(f));
    return u;
}

__device__ __forceinline__ void mma_tf32(float* c, const unsigned a[4], const unsigned b[2]) {
    asm volatile(
        "mma.sync.aligned.m16n8k8.row.col.f32.tf32.tf32.f32 "
        "{%0,%1,%2,%3},{%4,%5,%6,%7},{%8,%9},{%0,%1,%2,%3};"
        : "+f"(c[0]), "+f"(c[1]), "+f"(c[2]), "+f"(c[3])
        : "r"(a[0]), "r"(a[1]), "r"(a[2]), "r"(a[3]), "r"(b[0]), "r"(b[1]));
}

// ---------------------------------------------------------------------------
// tf32 GEMM (unchanged from round 3): C = A[M,K] @ W[Nn,K]^T + bias.
// ---------------------------------------------------------------------------
template <int MODE>
__global__ __launch_bounds__(256, 2) void tgemm(
    const float* __restrict__ A, const float* __restrict__ W,
    const float* __restrict__ bias, float* __restrict__ C,
    int M, int Nn, int K)
{
    __shared__ unsigned As[2][128][20];
    __shared__ unsigned Bs[2][128][20];

    const int tid = threadIdx.x;
    const int bm = blockIdx.y * 128, bn = blockIdx.x * 128;
    const int w = tid >> 5, lane = tid & 31;
    const int gid = lane >> 2, tig = lane & 3;
    const int wm = (w & 1) * 64, wn = (w >> 1) * 32;
    const int lr = tid >> 2, lc = (tid & 3) << 2;

    float acc[4][4][4];
#pragma unroll
    for (int mt = 0; mt < 4; mt++)
#pragma unroll
        for (int nt = 0; nt < 4; nt++)
#pragma unroll
            for (int i = 0; i < 4; i++) acc[mt][nt][i] = 0.f;

    const float* Ap0 = A + (size_t)(bm + lr) * K + lc;
    const float* Ap1 = A + (size_t)(bm + lr + 64) * K + lc;
    const float* Wp0 = W + (size_t)(bn + lr) * K + lc;
    const float* Wp1 = W + (size_t)(bn + lr + 64) * K + lc;

    float4 va0 = *(const float4*)Ap0;
    float4 va1 = *(const float4*)Ap1;
    float4 vb0 = *(const float4*)Wp0;
    float4 vb1 = *(const float4*)Wp1;

    {
        uint4 u;
        u.x = f2tf(va0.x); u.y = f2tf(va0.y); u.z = f2tf(va0.z); u.w = f2tf(va0.w);
        *(uint4*)&As[0][lr][lc] = u;
        u.x = f2tf(va1.x); u.y = f2tf(va1.y); u.z = f2tf(va1.z); u.w = f2tf(va1.w);
        *(uint4*)&As[0][lr + 64][lc] = u;
        u.x = f2tf(vb0.x); u.y = f2tf(vb0.y); u.z = f2tf(vb0.z); u.w = f2tf(vb0.w);
        *(uint4*)&Bs[0][lr][lc] = u;
        u.x = f2tf(vb1.x); u.y = f2tf(vb1.y); u.z = f2tf(vb1.z); u.w = f2tf(vb1.w);
        *(uint4*)&Bs[0][lr + 64][lc] = u;
    }
    __syncthreads();

    const int NC = K >> 4;
    for (int c = 0; c < NC; c++) {
        const int cur = c & 1;
        if (c + 1 < NC) {
            va0 = *(const float4*)(Ap0 + (c + 1) * 16);
            va1 = *(const float4*)(Ap1 + (c + 1) * 16);
            vb0 = *(const float4*)(Wp0 + (c + 1) * 16);
            vb1 = *(const float4*)(Wp1 + (c + 1) * 16);
        }
#pragma unroll
        for (int ks = 0; ks < 16; ks += 8) {
            unsigned af[4][4], bf[4][2];
#pragma unroll
            for (int mt = 0; mt < 4; mt++) {
                int m = wm + mt * 16;
                af[mt][0] = As[cur][m + gid][ks + tig];
                af[mt][1] = As[cur][m + gid + 8][ks + tig];
                af[mt][2] = As[cur][m + gid][ks + tig + 4];
                af[mt][3] = As[cur][m + gid + 8][ks + tig + 4];
            }
#pragma unroll
            for (int nt = 0; nt < 4; nt++) {
                int n = wn + nt * 8;
                bf[nt][0] = Bs[cur][n + gid][ks + tig];
                bf[nt][1] = Bs[cur][n + gid][ks + tig + 4];
            }
#pragma unroll
            for (int mt = 0; mt < 4; mt++)
#pragma unroll
                for (int nt = 0; nt < 4; nt++)
                    mma_tf32(acc[mt][nt], af[mt], bf[nt]);
        }
        if (c + 1 < NC) {
            const int nxt = cur ^ 1;
            uint4 u;
            u.x = f2tf(va0.x); u.y = f2tf(va0.y); u.z = f2tf(va0.z); u.w = f2tf(va0.w);
            *(uint4*)&As[nxt][lr][lc] = u;
            u.x = f2tf(va1.x); u.y = f2tf(va1.y); u.z = f2tf(va1.z); u.w = f2tf(va1.w);
            *(uint4*)&As[nxt][lr + 64][lc] = u;
            u.x = f2tf(vb0.x); u.y = f2tf(vb0.y); u.z = f2tf(vb0.z); u.w = f2tf(vb0.w);
            *(uint4*)&Bs[nxt][lr][lc] = u;
            u.x = f2tf(vb1.x); u.y = f2tf(vb1.y); u.z = f2tf(vb1.z); u.w = f2tf(vb1.w);
            *(uint4*)&Bs[nxt][lr + 64][lc] = u;
        }
        __syncthreads();
    }

#pragma unroll
    for (int mt = 0; mt < 4; mt++) {
#pragma unroll
        for (int nt = 0; nt < 4; nt++) {
            int r0 = bm + wm + mt * 16 + gid;
            int c0 = bn + wn + nt * 8 + 2 * tig;
            float v00 = acc[mt][nt][0] + bias[c0];
            float v01 = acc[mt][nt][1] + bias[c0 + 1];
            float v10 = acc[mt][nt][2] + bias[c0];
            float v11 = acc[mt][nt][3] + bias[c0 + 1];
            if (MODE == 0) {
                C[(size_t)r0 * Nn + c0]           = v00;
                C[(size_t)r0 * Nn + c0 + 1]       = v01;
                C[(size_t)(r0 + 8) * Nn + c0]     = v10;
                C[(size_t)(r0 + 8) * Nn + c0 + 1] = v11;
            } else {
#pragma unroll
                for (int p = 0; p < 4; p++) {
                    int m = (p < 2) ? r0 : (r0 + 8);
                    int e = c0 + (p & 1);
                    float v = (p == 0) ? v00 : (p == 1) ? v01 : (p == 2) ? v10 : v11;
                    int bb = m >> 11;
                    int n = m & 2047;
                    int which = e >> 10;
                    int hh = (e >> 6) & 15;
                    int d = e & 63;
                    size_t idx = ((size_t)(bb * H_ + hh) * N_ + n) * D_ + d;
                    if (which == 0)      g_Q[idx] = v * SCALE_;
                    else if (which == 1) g_K[idx] = v;
                    else                 g_V[idx] = v;
                }
            }
        }
    }
}

// ---------------------------------------------------------------------------
// Attention v3: CTA = 256 q rows, 8 warps, warp = 32q (two m16 blocks) x 32 kv.
// K/V fragments reused 2x per load. Bias = mma accumulator init (latency
// hidden under QK). kv tile 32, double-buffered, one sync per tile.
// ---------------------------------------------------------------------------
__global__ __launch_bounds__(256) void attn_kernel(
    const float* __restrict__ bias, const unsigned char* __restrict__ mask)
{
    __shared__ unsigned Ksm[2][32][68];
    __shared__ unsigned Vsm[2][32][72];

    const int tid = threadIdx.x;
    const int w = tid >> 5, lane = tid & 31;
    const int gid = lane >> 2, tig = lane & 3;
    const int b = blockIdx.x, q0 = blockIdx.y * 256, h = blockIdx.z;
    const int qb = q0 + w * 32;                 // warp's 32 q rows

    const size_t bh = (size_t)(b * H_ + h) * N_ * D_;
    const float* Qg = g_Q + bh;
    const float* Kg = g_K + bh;
    const float* Vg = g_V + bh;
    const float* bias_h = bias + (size_t)h * N_ * N_;
    const unsigned char* maskb = mask + (size_t)b * N_;

    // per-lane bias row pointers: rows qb + j*8 + gid, j = 0..3
    const float* bp[4];
#pragma unroll
    for (int j = 0; j < 4; j++) bp[j] = bias_h + (size_t)(qb + j * 8 + gid) * N_;

    // Q fragments, register resident: qf[kc][mb][4]
    unsigned qf[8][2][4];
#pragma unroll
    for (int kc = 0; kc < 8; kc++)
#pragma unroll
        for (int mb = 0; mb < 2; mb++) {
            int r = qb + mb * 16 + gid;
            qf[kc][mb][0] = f2tf(Qg[(size_t)r * D_ + kc * 8 + tig]);
            qf[kc][mb][1] = f2tf(Qg[(size_t)(r + 8) * D_ + kc * 8 + tig]);
            qf[kc][mb][2] = f2tf(Qg[(size_t)r * D_ + kc * 8 + tig + 4]);
            qf[kc][mb][3] = f2tf(Qg[(size_t)(r + 8) * D_ + kc * 8 + tig + 4]);
        }

    // K/V tile loader: thread -> row tid>>3 (0..31), cols (tid&7)*8 .. +7
    const int r_ld = tid >> 3, c_ld = (tid & 7) * 8;
    float4 pk[2], pv[2];
#pragma unroll
    for (int t = 0; t < 2; t++) {
        pk[t] = *(const float4*)(Kg + (size_t)r_ld * D_ + c_ld + t * 4);
        pv[t] = *(const float4*)(Vg + (size_t)r_ld * D_ + c_ld + t * 4);
    }
#pragma unroll
    for (int t = 0; t < 2; t++) {
        uint4 u;
        u.x = f2tf(pk[t].x); u.y = f2tf(pk[t].y); u.z = f2tf(pk[t].z); u.w = f2tf(pk[t].w);
        *(uint4*)&Ksm[0][r_ld][c_ld + t * 4] = u;
        u.x = f2tf(pv[t].x); u.y = f2tf(pv[t].y); u.z = f2tf(pv[t].z); u.w = f2tf(pv[t].w);
        *(uint4*)&Vsm[0][r_ld][c_ld + t * 4] = u;
    }
    __syncthreads();

    float m[4], l[4];
#pragma unroll
    for (int j = 0; j < 4; j++) { m[j] = -1e30f; l[j] = 0.f; }

    float o[8][8];
#pragma unroll
    for (int nt = 0; nt < 8; nt++)
#pragma unroll
        for (int i = 0; i < 8; i++) o[nt][i] = 0.f;

    const int NT = N_ / 32;
    for (int kti = 0; kti < NT; kti++) {
        const int cur = kti & 1;
        const int kt = kti * 32;

        // gmem prefetch for next tile
        if (kti + 1 < NT) {
            const float* Kn = Kg + (size_t)(kt + 32 + r_ld) * D_ + c_ld;
            const float* Vn = Vg + (size_t)(kt + 32 + r_ld) * D_ + c_ld;
#pragma unroll
            for (int t = 0; t < 2; t++) {
                pk[t] = *(const float4*)(Kn + t * 4);
                pv[t] = *(const float4*)(Vn + t * 4);
            }
        }

        // s init = bias (loads issue here; latency hidden under QK mma chain)
        float s[4][8];
#pragma unroll
        for (int nt = 0; nt < 4; nt++) {
            const int cc = kt + nt * 8 + 2 * tig;
#pragma unroll
            for (int j = 0; j < 4; j++) {
                float2 bz = *(const float2*)(bp[j] + cc);
                s[nt][j * 2 + 0] = bz.x;
                s[nt][j * 2 + 1] = bz.y;
            }
        }

        // s += Q @ K^T
#pragma unroll
        for (int kc = 0; kc < 8; kc++) {
#pragma unroll
            for (int nt = 0; nt < 4; nt++) {
                unsigned bb[2];
                bb[0] = Ksm[cur][nt * 8 + gid][kc * 8 + tig];
                bb[1] = Ksm[cur][nt * 8 + gid][kc * 8 + tig + 4];
                mma_tf32(&s[nt][0], qf[kc][0], bb);
                mma_tf32(&s[nt][4], qf[kc][1], bb);
            }
        }

        // mask
#pragma unroll
        for (int nt = 0; nt < 4; nt++) {
            uchar2 mk = *(const uchar2*)(maskb + kt + nt * 8 + 2 * tig);
            if (mk.x) { s[nt][0] = -1e30f; s[nt][2] = -1e30f; s[nt][4] = -1e30f; s[nt][6] = -1e30f; }
            if (mk.y) { s[nt][1] = -1e30f; s[nt][3] = -1e30f; s[nt][5] = -1e30f; s[nt][7] = -1e30f; }
        }

        // online softmax: 4 row-stats per lane (rows qb + j*8 + gid)
        float tm[4];
#pragma unroll
        for (int j = 0; j < 4; j++) tm[j] = -1e30f;
#pragma unroll
        for (int nt = 0; nt < 4; nt++) {
            tm[0] = fmaxf(tm[0], fmaxf(s[nt][0], s[nt][1]));
            tm[1] = fmaxf(tm[1], fmaxf(s[nt][2], s[nt][3]));
            tm[2] = fmaxf(tm[2], fmaxf(s[nt][4], s[nt][5]));
            tm[3] = fmaxf(tm[3], fmaxf(s[nt][6], s[nt][7]));
        }
        float al[4];
#pragma unroll
        for (int j = 0; j < 4; j++) {
            tm[j] = fmaxf(tm[j], __shfl_xor_sync(0xffffffffu, tm[j], 1));
            tm[j] = fmaxf(tm[j], __shfl_xor_sync(0xffffffffu, tm[j], 2));
            float mn = fmaxf(m[j], tm[j]);
            al[j] = __expf(m[j] - mn);
            m[j] = mn;
        }

        float ps[4] = {0.f, 0.f, 0.f, 0.f};
#pragma unroll
        for (int nt = 0; nt < 4; nt++) {
#pragma unroll
            for (int j = 0; j < 4; j++) {
                float p0 = __uint_as_float(f2tf(__expf(s[nt][j * 2 + 0] - m[j])));
                float p1 = __uint_as_float(f2tf(__expf(s[nt][j * 2 + 1] - m[j])));
                ps[j] += p0 + p1;
                s[nt][j * 2 + 0] = p0;
                s[nt][j * 2 + 1] = p1;
            }
        }
#pragma unroll
        for (int j = 0; j < 4; j++) {
            ps[j] += __shfl_xor_sync(0xffffffffu, ps[j], 1);
            ps[j] += __shfl_xor_sync(0xffffffffu, ps[j], 2);
            l[j] = l[j] * al[j] + ps[j];
        }

        // rescale O
#pragma unroll
        for (int nt = 0; nt < 8; nt++) {
            o[nt][0] *= al[0]; o[nt][1] *= al[0];
            o[nt][2] *= al[1]; o[nt][3] *= al[1];
            o[nt][4] *= al[2]; o[nt][5] *= al[2];
            o[nt][6] *= al[3]; o[nt][7] *= al[3];
        }

        // O += P @ V  (C-frag -> A-frag remap via quad shuffles, per m-block)
        const int src1 = (lane & ~3) | (tig >> 1);
        const int src2 = src1 + 2;
#pragma unroll
        for (int kc = 0; kc < 4; kc++) {
            unsigned a[2][4];
#pragma unroll
            for (int mb = 0; mb < 2; mb++) {
                float e00 = __shfl_sync(0xffffffffu, s[kc][mb * 4 + 0], src1);
                float e01 = __shfl_sync(0xffffffffu, s[kc][mb * 4 + 1], src1);
                float e20 = __shfl_sync(0xffffffffu, s[kc][mb * 4 + 2], src1);
                float e21 = __shfl_sync(0xffffffffu, s[kc][mb * 4 + 3], src1);
                float f00 = __shfl_sync(0xffffffffu, s[kc][mb * 4 + 0], src2);
                float f01 = __shfl_sync(0xffffffffu, s[kc][mb * 4 + 1], src2);
                float f20 = __shfl_sync(0xffffffffu, s[kc][mb * 4 + 2], src2);
                float f21 = __shfl_sync(0xffffffffu, s[kc][mb * 4 + 3], src2);
                a[mb][0] = __float_as_uint((tig & 1) ? e01 : e00);
                a[mb][1] = __float_as_uint((tig & 1) ? e21 : e20);
                a[mb][2] = __float_as_uint((tig & 1) ? f01 : f00);
                a[mb][3] = __float_as_uint((tig & 1) ? f21 : f20);
            }
#pragma unroll
            for (int nt = 0; nt < 8; nt++) {
                unsigned bb[2];
                bb[0] = Vsm[cur][kc * 8 + tig][nt * 8 + gid];
                bb[1] = Vsm[cur][kc * 8 + tig + 4][nt * 8 + gid];
                mma_tf32(&o[nt][0], a[0], bb);
                mma_tf32(&o[nt][4], a[1], bb);
            }
        }

        // stage next tile
        if (kti + 1 < NT) {
            const int nxt = cur ^ 1;
#pragma unroll
            for (int t = 0; t < 2; t++) {
                uint4 u;
                u.x = f2tf(pk[t].x); u.y = f2tf(pk[t].y); u.z = f2tf(pk[t].z); u.w = f2tf(pk[t].w);
                *(uint4*)&Ksm[nxt][r_ld][c_ld + t * 4] = u;
                u.x = f2tf(pv[t].x); u.y = f2tf(pv[t].y); u.z = f2tf(pv[t].z); u.w = f2tf(pv[t].w);
                *(uint4*)&Vsm[nxt][r_ld][c_ld + t * 4] = u;
            }
        }
        __syncthreads();
    }

    // epilogue: rows qb + mb*16 + gid (+8), cols h*64 + nt*8 + 2tig
    float inv[4];
#pragma unroll
    for (int j = 0; j < 4; j++) inv[j] = 1.f / l[j];
#pragma unroll
    for (int mb = 0; mb < 2; mb++) {
        int r = q0 + w * 32 + mb * 16 + gid;
        float* dst0 = g_AO + (size_t)(b * N_ + r) * DIM_ + h * D_;
        float* dst1 = dst0 + 8 * DIM_;
#pragma unroll
        for (int nt = 0; nt < 8; nt++) {
            int cc = nt * 8 + 2 * tig;
            float2 v0 = make_float2(o[nt][mb * 4 + 0] * inv[mb * 2],
                                    o[nt][mb * 4 + 1] * inv[mb * 2]);
            float2 v1 = make_float2(o[nt][mb * 4 + 2] * inv[mb * 2 + 1],
                                    o[nt][mb * 4 + 3] * inv[mb * 2 + 1]);
            *(float2*)(dst0 + cc) = v0;
            *(float2*)(dst1 + cc) = v1;
        }
    }
}

// ---------------------------------------------------------------------------
extern "C" void kernel_launch(void* const* d_in, const int* in_sizes, int n_in,
                              void* d_out, int out_size)
{
    (void)in_sizes; (void)n_in; (void)out_size;
    const float* x         = (const float*)d_in[0];
    const float* attn_bias = (const float*)d_in[1];
    const unsigned char* key_padding_mask = (const unsigned char*)d_in[2];
    const float* qkv_w     = (const float*)d_in[3];
    const float* qkv_b     = (const float*)d_in[4];
    const float* proj_w    = (const float*)d_in[5];
    const float* proj_b    = (const float*)d_in[6];
    float* out = (float*)d_out;

    dim3 g1(E3_ / 128, (B_ * N_) / 128);   // 24 x 32
    tgemm<1><<<g1, 256>>>(x, qkv_w, qkv_b, nullptr, B_ * N_, E3_, DIM_);

    dim3 g2(B_, N_ / 256, H_);             // 2 x 8 x 16 = 256 CTAs
    attn_kernel<<<g2, 256>>>(attn_bias, key_padding_mask);

    void* pAO = nullptr;
    cudaGetSymbolAddress(&pAO, g_AO);
    dim3 g3(DIM_ / 128, (B_ * N_) / 128);  // 8 x 32
    tgemm<0><<<g3, 256>>>((const float*)pAO, proj_w, proj_b, out,
                          B_ * N_, DIM_, DIM_);
}

// round 5
// speedup vs baseline: 3.3960x; 1.1808x over previous
#include <cuda_runtime.h>

#define B_    2
#define N_    2048
#define DIM_  1024
#define H_    16
#define D_    64
#define E3_   3072
#define SCALE_ 0.125f

// Scratch (no allocations allowed)
__device__ float g_Q[B_ * H_ * N_ * D_];
__device__ float g_K[B_ * H_ * N_ * D_];
__device__ float g_V[B_ * H_ * N_ * D_];
__device__ float g_AO[B_ * N_ * DIM_];

__device__ __forceinline__ unsigned f2tf(float f) {
    unsigned u;
    asm("cvt.rna.tf32.f32 %0, %1;" : "=r"(u) : "f"(f));
    return u;
}

__device__ __forceinline__ void mma_tf32(float* c, const unsigned a[4], const unsigned b[2]) {
    asm volatile(
        "mma.sync.aligned.m16n8k8.row.col.f32.tf32.tf32.f32 "
        "{%0,%1,%2,%3},{%4,%5,%6,%7},{%8,%9},{%0,%1,%2,%3};"
        : "+f"(c[0]), "+f"(c[1]), "+f"(c[2]), "+f"(c[3])
        : "r"(a[0]), "r"(a[1]), "r"(a[2]), "r"(a[3]), "r"(b[0]), "r"(b[1]));
}

__device__ __forceinline__ void ldsm4(unsigned& r0, unsigned& r1, unsigned& r2, unsigned& r3,
                                      unsigned addr) {
    asm volatile("ldmatrix.sync.aligned.m8n8.x4.shared.b16 {%0,%1,%2,%3}, [%4];"
                 : "=r"(r0), "=r"(r1), "=r"(r2), "=r"(r3) : "r"(addr));
}

__device__ __forceinline__ unsigned smaddr(const void* p) {
    return (unsigned)__cvta_generic_to_shared(p);
}

// ---------------------------------------------------------------------------
// tf32 GEMM: C = A[M,K] @ W[Nn,K]^T + bias. ldmatrix fragment loads.
// ---------------------------------------------------------------------------
template <int MODE>
__global__ __launch_bounds__(256, 2) void tgemm(
    const float* __restrict__ A, const float* __restrict__ W,
    const float* __restrict__ bias, float* __restrict__ C,
    int M, int Nn, int K)
{
    __shared__ unsigned As[2][128][20];
    __shared__ unsigned Bs[2][128][20];

    const int tid = threadIdx.x;
    const int bm = blockIdx.y * 128, bn = blockIdx.x * 128;
    const int w = tid >> 5, lane = tid & 31;
    const int gid = lane >> 2, tig = lane & 3;
    const int wm = (w & 1) * 64, wn = (w >> 1) * 32;
    const int lr = tid >> 2, lc = (tid & 3) << 2;

    // per-lane ldmatrix byte offsets within a [128][20] tile
    const unsigned a_off = ((((lane & 7) + ((lane >> 3) & 1) * 8) * 20) + (lane >> 4) * 4) * 4;
    const unsigned b_off = ((((lane & 7) + (lane >> 4) * 8) * 20) + ((lane >> 3) & 1) * 4) * 4;
    const unsigned As_base = smaddr(&As[0][0][0]);
    const unsigned Bs_base = smaddr(&Bs[0][0][0]);
    const unsigned STG_STRIDE = 128 * 20 * 4;

    float acc[4][4][4];
#pragma unroll
    for (int mt = 0; mt < 4; mt++)
#pragma unroll
        for (int nt = 0; nt < 4; nt++)
#pragma unroll
            for (int i = 0; i < 4; i++) acc[mt][nt][i] = 0.f;

    const float* Ap0 = A + (size_t)(bm + lr) * K + lc;
    const float* Ap1 = A + (size_t)(bm + lr + 64) * K + lc;
    const float* Wp0 = W + (size_t)(bn + lr) * K + lc;
    const float* Wp1 = W + (size_t)(bn + lr + 64) * K + lc;

    float4 va0 = *(const float4*)Ap0;
    float4 va1 = *(const float4*)Ap1;
    float4 vb0 = *(const float4*)Wp0;
    float4 vb1 = *(const float4*)Wp1;

    {
        uint4 u;
        u.x = f2tf(va0.x); u.y = f2tf(va0.y); u.z = f2tf(va0.z); u.w = f2tf(va0.w);
        *(uint4*)&As[0][lr][lc] = u;
        u.x = f2tf(va1.x); u.y = f2tf(va1.y); u.z = f2tf(va1.z); u.w = f2tf(va1.w);
        *(uint4*)&As[0][lr + 64][lc] = u;
        u.x = f2tf(vb0.x); u.y = f2tf(vb0.y); u.z = f2tf(vb0.z); u.w = f2tf(vb0.w);
        *(uint4*)&Bs[0][lr][lc] = u;
        u.x = f2tf(vb1.x); u.y = f2tf(vb1.y); u.z = f2tf(vb1.z); u.w = f2tf(vb1.w);
        *(uint4*)&Bs[0][lr + 64][lc] = u;
    }
    __syncthreads();

    const int NC = K >> 4;
    for (int c = 0; c < NC; c++) {
        const int cur = c & 1;
        if (c + 1 < NC) {
            va0 = *(const float4*)(Ap0 + (c + 1) * 16);
            va1 = *(const float4*)(Ap1 + (c + 1) * 16);
            vb0 = *(const float4*)(Wp0 + (c + 1) * 16);
            vb1 = *(const float4*)(Wp1 + (c + 1) * 16);
        }
        const unsigned Abase = As_base + cur * STG_STRIDE;
        const unsigned Bbase = Bs_base + cur * STG_STRIDE;
#pragma unroll
        for (int ks = 0; ks < 16; ks += 8) {
            unsigned af[4][4], bf[4][2];
#pragma unroll
            for (int mt = 0; mt < 4; mt++)
                ldsm4(af[mt][0], af[mt][1], af[mt][2], af[mt][3],
                      Abase + (unsigned)((wm + mt * 16) * 20 + ks) * 4 + a_off);
#pragma unroll
            for (int ntp = 0; ntp < 4; ntp += 2)
                ldsm4(bf[ntp][0], bf[ntp][1], bf[ntp + 1][0], bf[ntp + 1][1],
                      Bbase + (unsigned)((wn + ntp * 8) * 20 + ks) * 4 + b_off);
#pragma unroll
            for (int mt = 0; mt < 4; mt++)
#pragma unroll
                for (int nt = 0; nt < 4; nt++)
                    mma_tf32(acc[mt][nt], af[mt], bf[nt]);
        }
        if (c + 1 < NC) {
            const int nxt = cur ^ 1;
            uint4 u;
            u.x = f2tf(va0.x); u.y = f2tf(va0.y); u.z = f2tf(va0.z); u.w = f2tf(va0.w);
            *(uint4*)&As[nxt][lr][lc] = u;
            u.x = f2tf(va1.x); u.y = f2tf(va1.y); u.z = f2tf(va1.z); u.w = f2tf(va1.w);
            *(uint4*)&As[nxt][lr + 64][lc] = u;
            u.x = f2tf(vb0.x); u.y = f2tf(vb0.y); u.z = f2tf(vb0.z); u.w = f2tf(vb0.w);
            *(uint4*)&Bs[nxt][lr][lc] = u;
            u.x = f2tf(vb1.x); u.y = f2tf(vb1.y); u.z = f2tf(vb1.z); u.w = f2tf(vb1.w);
            *(uint4*)&Bs[nxt][lr + 64][lc] = u;
        }
        __syncthreads();
    }

#pragma unroll
    for (int mt = 0; mt < 4; mt++) {
#pragma unroll
        for (int nt = 0; nt < 4; nt++) {
            int r0 = bm + wm + mt * 16 + gid;
            int c0 = bn + wn + nt * 8 + 2 * tig;
            float v00 = acc[mt][nt][0] + bias[c0];
            float v01 = acc[mt][nt][1] + bias[c0 + 1];
            float v10 = acc[mt][nt][2] + bias[c0];
            float v11 = acc[mt][nt][3] + bias[c0 + 1];
            if (MODE == 0) {
                C[(size_t)r0 * Nn + c0]           = v00;
                C[(size_t)r0 * Nn + c0 + 1]       = v01;
                C[(size_t)(r0 + 8) * Nn + c0]     = v10;
                C[(size_t)(r0 + 8) * Nn + c0 + 1] = v11;
            } else {
#pragma unroll
                for (int p = 0; p < 4; p++) {
                    int m = (p < 2) ? r0 : (r0 + 8);
                    int e = c0 + (p & 1);
                    float v = (p == 0) ? v00 : (p == 1) ? v01 : (p == 2) ? v10 : v11;
                    int bb = m >> 11;
                    int n = m & 2047;
                    int which = e >> 10;
                    int hh = (e >> 6) & 15;
                    int d = e & 63;
                    size_t idx = ((size_t)(bb * H_ + hh) * N_ + n) * D_ + d;
                    if (which == 0)      g_Q[idx] = v * SCALE_;
                    else if (which == 1) g_K[idx] = v;
                    else                 g_V[idx] = v;
                }
            }
        }
    }
}

// ---------------------------------------------------------------------------
// Attention v4: bias via cp.async double-buffered smem (latency hidden),
// K-fragments via ldmatrix.x4. Warp = 32q x 32kv, kv tile 32, double buffer.
// ---------------------------------------------------------------------------
#define KW 68
#define VW 72
#define BW 40
#define KS_STRIDE (32 * KW)
#define VS_STRIDE (32 * VW)
#define BI_STRIDE (256 * BW)

__global__ __launch_bounds__(256) void attn_kernel(
    const float* __restrict__ bias, const unsigned char* __restrict__ mask)
{
    extern __shared__ unsigned dsm[];
    unsigned* Ksm = dsm;                              // [2][32][KW]
    unsigned* Vsm = dsm + 2 * KS_STRIDE;              // [2][32][VW]
    float*    Bi  = (float*)(dsm + 2 * KS_STRIDE + 2 * VS_STRIDE);  // [2][256][BW]

    const int tid = threadIdx.x;
    const int w = tid >> 5, lane = tid & 31;
    const int gid = lane >> 2, tig = lane & 3;
    const int b = blockIdx.x, q0 = blockIdx.y * 256, h = blockIdx.z;
    const int qb = q0 + w * 32;

    const size_t bh = (size_t)(b * H_ + h) * N_ * D_;
    const float* Qg = g_Q + bh;
    const float* Kg = g_K + bh;
    const float* Vg = g_V + bh;
    const float* bias_h = bias + (size_t)h * N_ * N_;
    const unsigned char* maskb = mask + (size_t)b * N_;

    const unsigned ksm_base = smaddr(Ksm);
    const unsigned bi_base  = smaddr(Bi);
    // per-lane ldmatrix byte offset within K tile: row (lane&7), col quadrant (lane>>3)*4
    const unsigned k_off = (((lane & 7) * KW) + (lane >> 3) * 4) * 4;

    // bias cp.async mapping: thread -> row tid>>3 (+32p), 4 floats at (tid&7)*4
    const int brow = tid >> 3, bcol = (tid & 7) * 4;

    // Q fragments, register resident
    unsigned qf[8][2][4];
#pragma unroll
    for (int kc = 0; kc < 8; kc++)
#pragma unroll
        for (int mb = 0; mb < 2; mb++) {
            int r = qb + mb * 16 + gid;
            qf[kc][mb][0] = f2tf(Qg[(size_t)r * D_ + kc * 8 + tig]);
            qf[kc][mb][1] = f2tf(Qg[(size_t)(r + 8) * D_ + kc * 8 + tig]);
            qf[kc][mb][2] = f2tf(Qg[(size_t)r * D_ + kc * 8 + tig + 4]);
            qf[kc][mb][3] = f2tf(Qg[(size_t)(r + 8) * D_ + kc * 8 + tig + 4]);
        }

    // issue bias stage 0 (kt = 0)
#pragma unroll
    for (int p = 0; p < 8; p++) {
        int r = brow + p * 32;
        const float* src = bias_h + (size_t)(q0 + r) * N_ + bcol;
        unsigned dst = bi_base + (unsigned)(r * BW + bcol) * 4;
        asm volatile("cp.async.ca.shared.global [%0], [%1], 16;" :: "r"(dst), "l"(src));
    }
    asm volatile("cp.async.commit_group;");

    // K/V stage 0
    const int r_ld = tid >> 3, c_ld = (tid & 7) * 8;
    float4 pk[2], pv[2];
#pragma unroll
    for (int t = 0; t < 2; t++) {
        pk[t] = *(const float4*)(Kg + (size_t)r_ld * D_ + c_ld + t * 4);
        pv[t] = *(const float4*)(Vg + (size_t)r_ld * D_ + c_ld + t * 4);
    }
#pragma unroll
    for (int t = 0; t < 2; t++) {
        uint4 u;
        u.x = f2tf(pk[t].x); u.y = f2tf(pk[t].y); u.z = f2tf(pk[t].z); u.w = f2tf(pk[t].w);
        *(uint4*)&Ksm[r_ld * KW + c_ld + t * 4] = u;
        u.x = f2tf(pv[t].x); u.y = f2tf(pv[t].y); u.z = f2tf(pv[t].z); u.w = f2tf(pv[t].w);
        *(uint4*)&Vsm[r_ld * VW + c_ld + t * 4] = u;
    }
    asm volatile("cp.async.wait_group 0;");
    __syncthreads();

    float m[4], l[4];
#pragma unroll
    for (int j = 0; j < 4; j++) { m[j] = -1e30f; l[j] = 0.f; }

    float o[8][8];
#pragma unroll
    for (int nt = 0; nt < 8; nt++)
#pragma unroll
        for (int i = 0; i < 8; i++) o[nt][i] = 0.f;

    const int NT = N_ / 32;
    for (int kti = 0; kti < NT; kti++) {
        const int cur = kti & 1;
        const int nxt = cur ^ 1;
        const int kt = kti * 32;
        const bool more = (kti + 1 < NT);

        // bias cp.async for next tile (completes during this body)
        if (more) {
#pragma unroll
            for (int p = 0; p < 8; p++) {
                int r = brow + p * 32;
                const float* src = bias_h + (size_t)(q0 + r) * N_ + kt + 32 + bcol;
                unsigned dst = bi_base + (unsigned)(nxt * BI_STRIDE + r * BW + bcol) * 4;
                asm volatile("cp.async.ca.shared.global [%0], [%1], 16;" :: "r"(dst), "l"(src));
            }
            asm volatile("cp.async.commit_group;");
            // K/V gmem prefetch
            const float* Kn = Kg + (size_t)(kt + 32 + r_ld) * D_ + c_ld;
            const float* Vn = Vg + (size_t)(kt + 32 + r_ld) * D_ + c_ld;
#pragma unroll
            for (int t = 0; t < 2; t++) {
                pk[t] = *(const float4*)(Kn + t * 4);
                pv[t] = *(const float4*)(Vn + t * 4);
            }
        }

        // s init = bias from smem
        float s[4][8];
#pragma unroll
        for (int nt = 0; nt < 4; nt++) {
            const int cc = nt * 8 + 2 * tig;
#pragma unroll
            for (int j = 0; j < 4; j++) {
                float2 bz = *(const float2*)&Bi[cur * BI_STRIDE + (w * 32 + j * 8 + gid) * BW + cc];
                s[nt][j * 2 + 0] = bz.x;
                s[nt][j * 2 + 1] = bz.y;
            }
        }

        // s += Q @ K^T  (K frags via ldmatrix.x4: two kc per load)
        const unsigned kb = ksm_base + cur * KS_STRIDE * 4;
#pragma unroll
        for (int kcp = 0; kcp < 4; kcp++) {
#pragma unroll
            for (int nt = 0; nt < 4; nt++) {
                unsigned b0[2], b1[2];
                ldsm4(b0[0], b0[1], b1[0], b1[1],
                      kb + (unsigned)(nt * 8 * KW) * 4 + (unsigned)kcp * 64 + k_off);
                mma_tf32(&s[nt][0], qf[2 * kcp][0], b0);
                mma_tf32(&s[nt][4], qf[2 * kcp][1], b0);
                mma_tf32(&s[nt][0], qf[2 * kcp + 1][0], b1);
                mma_tf32(&s[nt][4], qf[2 * kcp + 1][1], b1);
            }
        }

        // mask
#pragma unroll
        for (int nt = 0; nt < 4; nt++) {
            uchar2 mk = *(const uchar2*)(maskb + kt + nt * 8 + 2 * tig);
            if (mk.x) { s[nt][0] = -1e30f; s[nt][2] = -1e30f; s[nt][4] = -1e30f; s[nt][6] = -1e30f; }
            if (mk.y) { s[nt][1] = -1e30f; s[nt][3] = -1e30f; s[nt][5] = -1e30f; s[nt][7] = -1e30f; }
        }

        // online softmax
        float tm[4];
#pragma unroll
        for (int j = 0; j < 4; j++) tm[j] = -1e30f;
#pragma unroll
        for (int nt = 0; nt < 4; nt++) {
            tm[0] = fmaxf(tm[0], fmaxf(s[nt][0], s[nt][1]));
            tm[1] = fmaxf(tm[1], fmaxf(s[nt][2], s[nt][3]));
            tm[2] = fmaxf(tm[2], fmaxf(s[nt][4], s[nt][5]));
            tm[3] = fmaxf(tm[3], fmaxf(s[nt][6], s[nt][7]));
        }
        float al[4];
#pragma unroll
        for (int j = 0; j < 4; j++) {
            tm[j] = fmaxf(tm[j], __shfl_xor_sync(0xffffffffu, tm[j], 1));
            tm[j] = fmaxf(tm[j], __shfl_xor_sync(0xffffffffu, tm[j], 2));
            float mn = fmaxf(m[j], tm[j]);
            al[j] = __expf(m[j] - mn);
            m[j] = mn;
        }

        float ps[4] = {0.f, 0.f, 0.f, 0.f};
#pragma unroll
        for (int nt = 0; nt < 4; nt++) {
#pragma unroll
            for (int j = 0; j < 4; j++) {
                float p0 = __uint_as_float(f2tf(__expf(s[nt][j * 2 + 0] - m[j])));
                float p1 = __uint_as_float(f2tf(__expf(s[nt][j * 2 + 1] - m[j])));
                ps[j] += p0 + p1;
                s[nt][j * 2 + 0] = p0;
                s[nt][j * 2 + 1] = p1;
            }
        }
#pragma unroll
        for (int j = 0; j < 4; j++) {
            ps[j] += __shfl_xor_sync(0xffffffffu, ps[j], 1);
            ps[j] += __shfl_xor_sync(0xffffffffu, ps[j], 2);
            l[j] = l[j] * al[j] + ps[j];
        }

#pragma unroll
        for (int nt = 0; nt < 8; nt++) {
            o[nt][0] *= al[0]; o[nt][1] *= al[0];
            o[nt][2] *= al[1]; o[nt][3] *= al[1];
            o[nt][4] *= al[2]; o[nt][5] *= al[2];
            o[nt][6] *= al[3]; o[nt][7] *= al[3];
        }

        // O += P @ V
        const int src1 = (lane & ~3) | (tig >> 1);
        const int src2 = src1 + 2;
        const unsigned* Vcur = Vsm + cur * VS_STRIDE;
#pragma unroll
        for (int kc = 0; kc < 4; kc++) {
            unsigned a[2][4];
#pragma unroll
            for (int mb = 0; mb < 2; mb++) {
                float e00 = __shfl_sync(0xffffffffu, s[kc][mb * 4 + 0], src1);
                float e01 = __shfl_sync(0xffffffffu, s[kc][mb * 4 + 1], src1);
                float e20 = __shfl_sync(0xffffffffu, s[kc][mb * 4 + 2], src1);
                float e21 = __shfl_sync(0xffffffffu, s[kc][mb * 4 + 3], src1);
                float f00 = __shfl_sync(0xffffffffu, s[kc][mb * 4 + 0], src2);
                float f01 = __shfl_sync(0xffffffffu, s[kc][mb * 4 + 1], src2);
                float f20 = __shfl_sync(0xffffffffu, s[kc][mb * 4 + 2], src2);
                float f21 = __shfl_sync(0xffffffffu, s[kc][mb * 4 + 3], src2);
                a[mb][0] = __float_as_uint((tig & 1) ? e01 : e00);
                a[mb][1] = __float_as_uint((tig & 1) ? e21 : e20);
                a[mb][2] = __float_as_uint((tig & 1) ? f01 : f00);
                a[mb][3] = __float_as_uint((tig & 1) ? f21 : f20);
            }
#pragma unroll
            for (int nt = 0; nt < 8; nt++) {
                unsigned bb[2];
                bb[0] = Vcur[(kc * 8 + tig) * VW + nt * 8 + gid];
                bb[1] = Vcur[(kc * 8 + tig + 4) * VW + nt * 8 + gid];
                mma_tf32(&o[nt][0], a[0], bb);
                mma_tf32(&o[nt][4], a[1], bb);
            }
        }

        // stage next K/V
        if (more) {
#pragma unroll
            for (int t = 0; t < 2; t++) {
                uint4 u;
                u.x = f2tf(pk[t].x); u.y = f2tf(pk[t].y); u.z = f2tf(pk[t].z); u.w = f2tf(pk[t].w);
                *(uint4*)&Ksm[nxt * KS_STRIDE + r_ld * KW + c_ld + t * 4] = u;
                u.x = f2tf(pv[t].x); u.y = f2tf(pv[t].y); u.z = f2tf(pv[t].z); u.w = f2tf(pv[t].w);
                *(uint4*)&Vsm[nxt * VS_STRIDE + r_ld * VW + c_ld + t * 4] = u;
            }
            asm volatile("cp.async.wait_group 0;");
        }
        __syncthreads();
    }

    // epilogue
    float inv[4];
#pragma unroll
    for (int j = 0; j < 4; j++) inv[j] = 1.f / l[j];
#pragma unroll
    for (int mb = 0; mb < 2; mb++) {
        int r = q0 + w * 32 + mb * 16 + gid;
        float* dst0 = g_AO + (size_t)(b * N_ + r) * DIM_ + h * D_;
        float* dst1 = dst0 + 8 * DIM_;
#pragma unroll
        for (int nt = 0; nt < 8; nt++) {
            int cc = nt * 8 + 2 * tig;
            float2 v0 = make_float2(o[nt][mb * 4 + 0] * inv[mb * 2],
                                    o[nt][mb * 4 + 1] * inv[mb * 2]);
            float2 v1 = make_float2(o[nt][mb * 4 + 2] * inv[mb * 2 + 1],
                                    o[nt][mb * 4 + 3] * inv[mb * 2 + 1]);
            *(float2*)(dst0 + cc) = v0;
            *(float2*)(dst1 + cc) = v1;
        }
    }
}

// ---------------------------------------------------------------------------
extern "C" void kernel_launch(void* const* d_in, const int* in_sizes, int n_in,
                              void* d_out, int out_size)
{
    (void)in_sizes; (void)n_in; (void)out_size;
    const float* x         = (const float*)d_in[0];
    const float* attn_bias = (const float*)d_in[1];
    const unsigned char* key_padding_mask = (const unsigned char*)d_in[2];
    const float* qkv_w     = (const float*)d_in[3];
    const float* qkv_b     = (const float*)d_in[4];
    const float* proj_w    = (const float*)d_in[5];
    const float* proj_b    = (const float*)d_in[6];
    float* out = (float*)d_out;

    const int ATTN_SMEM = (2 * KS_STRIDE + 2 * VS_STRIDE + 2 * BI_STRIDE) * 4;  // 117760 B
    cudaFuncSetAttribute(attn_kernel, cudaFuncAttributeMaxDynamicSharedMemorySize, ATTN_SMEM);

    dim3 g1(E3_ / 128, (B_ * N_) / 128);   // 24 x 32
    tgemm<1><<<g1, 256>>>(x, qkv_w, qkv_b, nullptr, B_ * N_, E3_, DIM_);

    dim3 g2(B_, N_ / 256, H_);             // 2 x 8 x 16 = 256 CTAs
    attn_kernel<<<g2, 256, ATTN_SMEM>>>(attn_bias, key_padding_mask);

    void* pAO = nullptr;
    cudaGetSymbolAddress(&pAO, g_AO);
    dim3 g3(DIM_ / 128, (B_ * N_) / 128);  // 8 x 32
    tgemm<0><<<g3, 256>>>((const float*)pAO, proj_w, proj_b, out,
                          B_ * N_, DIM_, DIM_);
}